// round 1
// baseline (speedup 1.0000x reference)
#include <cuda_runtime.h>
#include <math_constants.h>

#define B 16
#define T 32
#define WW 128
#define D 1024
#define NDBLK 16
#define DR (D / NDBLK)   // 64

// Scratch (no device allocation allowed)
__device__ float g_part[2 * NDBLK * B * D];  // projection partials [mat][dblk][b][c]
__device__ float g_cw[B * T * D];            // word-attended context per turn
__device__ float g_ts[B * T];                // turn scores

// ---------------------------------------------------------------------------
// Kernel 1: partial projections  q = source @ W  (W stored [indim, outdim])
// grid = 2 mats * 4 cblks * NDBLK dblks = 128 blocks, 256 threads
// Each block: 256 output columns, 64-deep slice of the reduction dim.
// Partials summed on the fly by the attention kernel (cheap, L2-resident).
// ---------------------------------------------------------------------------
__global__ __launch_bounds__(256) void proj_part_kernel(
    const float* __restrict__ src, const float* __restrict__ Wword,
    const float* __restrict__ Wturn) {
  int x = blockIdx.x;
  int mat = x >> 6;          // 0: W_word, 1: W_turn
  int cblk = (x >> 4) & 3;
  int dblk = x & 15;
  const float* Wm = mat ? Wturn : Wword;
  int c = cblk * 256 + threadIdx.x;
  int d0 = dblk * DR;

  __shared__ __align__(16) float s_src[DR][B];  // [d][b], 4 KB
  for (int e = threadIdx.x; e < DR * B; e += 256) {
    int dl = e >> 4, bb = e & 15;
    s_src[dl][bb] = src[bb * D + d0 + dl];
  }
  __syncthreads();

  float acc[B];
#pragma unroll
  for (int b = 0; b < B; b++) acc[b] = 0.f;

  for (int dl = 0; dl < DR; dl++) {
    float wv = Wm[(d0 + dl) * D + c];  // coalesced across threads
    const float4* sp = reinterpret_cast<const float4*>(s_src[dl]);
#pragma unroll
    for (int b4 = 0; b4 < 4; b4++) {
      float4 sv = sp[b4];
      acc[b4 * 4 + 0] = fmaf(sv.x, wv, acc[b4 * 4 + 0]);
      acc[b4 * 4 + 1] = fmaf(sv.y, wv, acc[b4 * 4 + 1]);
      acc[b4 * 4 + 2] = fmaf(sv.z, wv, acc[b4 * 4 + 2]);
      acc[b4 * 4 + 3] = fmaf(sv.w, wv, acc[b4 * 4 + 3]);
    }
  }

  float* outp = g_part + (mat * NDBLK + dblk) * B * D;
#pragma unroll
  for (int b = 0; b < B; b++) outp[b * D + c] = acc[b];
}

// ---------------------------------------------------------------------------
// Kernel 2: per-(b,t) word attention with ONLINE softmax (single pass).
// Skips masked turns (t >= memory_turns[b]) and masked words (w >= len).
// Each thread owns 4 contiguous D-columns (float4). Warp 0 does the softmax
// bookkeeping (exp is expensive if replicated) and broadcasts 4 row weights
// + a rescale factor per 4-row group.
// ---------------------------------------------------------------------------
__global__ __launch_bounds__(256) void attn_kernel(
    const float* __restrict__ bank, const int* __restrict__ lens,
    const int* __restrict__ turns) {
  int t = blockIdx.x, b = blockIdx.y;
  if (t >= turns[b]) return;  // masked turn: contributes exactly 0 downstream
  int len = lens[b * T + t];  // in [1, W]
  int tid = threadIdx.x;
  int c4 = tid * 4;

  // Reduce projection partials for this b (L2-resident, shared by 32 CTAs)
  float4 qw = make_float4(0.f, 0.f, 0.f, 0.f);
  float4 qt = make_float4(0.f, 0.f, 0.f, 0.f);
#pragma unroll
  for (int j = 0; j < NDBLK; j++) {
    float4 p = *reinterpret_cast<const float4*>(g_part + (j * B + b) * D + c4);
    qw.x += p.x; qw.y += p.y; qw.z += p.z; qw.w += p.w;
    float4 q = *reinterpret_cast<const float4*>(g_part + ((NDBLK + j) * B + b) * D + c4);
    qt.x += q.x; qt.y += q.y; qt.z += q.z; qt.w += q.w;
  }

  const float* base = bank + (long)(b * T + t) * WW * D;

  __shared__ float red_s[8][4];
  __shared__ float bcast[6];

  float4 acc = make_float4(0.f, 0.f, 0.f, 0.f);
  float m_run = -CUDART_INF_F, sum_run = 0.f;  // live in warp 0

  for (int w0 = 0; w0 < len; w0 += 4) {
    float4 r[4];
    float p[4];
#pragma unroll
    for (int i = 0; i < 4; i++) {
      if (w0 + i < len)
        r[i] = *reinterpret_cast<const float4*>(base + (w0 + i) * D + c4);
      else
        r[i] = make_float4(0.f, 0.f, 0.f, 0.f);
      p[i] = fmaf(qw.x, r[i].x, fmaf(qw.y, r[i].y, fmaf(qw.z, r[i].z, qw.w * r[i].w)));
    }
    // stage 1: warp reduce 4 partial dots
#pragma unroll
    for (int off = 16; off; off >>= 1) {
#pragma unroll
      for (int i = 0; i < 4; i++) p[i] += __shfl_down_sync(0xffffffffu, p[i], off);
    }
    if ((tid & 31) == 0) {
      int wp = tid >> 5;
      red_s[wp][0] = p[0]; red_s[wp][1] = p[1];
      red_s[wp][2] = p[2]; red_s[wp][3] = p[3];
    }
    __syncthreads();
    // stage 2 + online softmax math: warp 0 only
    if (tid < 32) {
      float v = red_s[tid >> 2][tid & 3];  // 8 warps x 4 rows
      v += __shfl_xor_sync(0xffffffffu, v, 4);
      v += __shfl_xor_sync(0xffffffffu, v, 8);
      v += __shfl_xor_sync(0xffffffffu, v, 16);
      float sarr[4];
      sarr[0] = __shfl_sync(0xffffffffu, v, 0);
      sarr[1] = __shfl_sync(0xffffffffu, v, 1);
      sarr[2] = __shfl_sync(0xffffffffu, v, 2);
      sarr[3] = __shfl_sync(0xffffffffu, v, 3);
      float S = 1.f, wgt[4];
#pragma unroll
      for (int i = 0; i < 4; i++) {
        float si = (w0 + i < len) ? sarr[i] : -CUDART_INF_F;
        float nm = fmaxf(m_run, si);
        float sc = __expf(m_run - nm);  // 0 on first valid row (m_run=-inf)
        float e  = __expf(si - nm);     // 0 on masked rows
        S *= sc;
#pragma unroll
        for (int j = 0; j < 4; j++)
          if (j < i) wgt[j] *= sc;
        wgt[i] = e;
        sum_run = fmaf(sum_run, sc, e);
        m_run = nm;
      }
      if (tid == 0) {
        bcast[0] = wgt[0]; bcast[1] = wgt[1];
        bcast[2] = wgt[2]; bcast[3] = wgt[3];
        bcast[4] = S;
      }
    }
    __syncthreads();
    float Sv  = bcast[4];
    float b0v = bcast[0], b1v = bcast[1], b2v = bcast[2], b3v = bcast[3];
    acc.x = fmaf(acc.x, Sv, fmaf(b0v, r[0].x, fmaf(b1v, r[1].x, fmaf(b2v, r[2].x, b3v * r[3].x))));
    acc.y = fmaf(acc.y, Sv, fmaf(b0v, r[0].y, fmaf(b1v, r[1].y, fmaf(b2v, r[2].y, b3v * r[3].y))));
    acc.z = fmaf(acc.z, Sv, fmaf(b0v, r[0].z, fmaf(b1v, r[1].z, fmaf(b2v, r[2].z, b3v * r[3].z))));
    acc.w = fmaf(acc.w, Sv, fmaf(b0v, r[0].w, fmaf(b1v, r[1].w, fmaf(b2v, r[2].w, b3v * r[3].w))));
  }

  if (tid == 0) bcast[5] = sum_run;
  __syncthreads();
  float inv = 1.f / bcast[5];
  float4 cw = make_float4(acc.x * inv, acc.y * inv, acc.z * inv, acc.w * inv);
  *reinterpret_cast<float4*>(g_cw + (b * T + t) * D + c4) = cw;

  // turn score: q_t . cw  (block reduce)
  float tp = fmaf(qt.x, cw.x, fmaf(qt.y, cw.y, fmaf(qt.z, cw.z, qt.w * cw.w)));
#pragma unroll
  for (int off = 16; off; off >>= 1) tp += __shfl_down_sync(0xffffffffu, tp, off);
  if ((tid & 31) == 0) red_s[tid >> 5][0] = tp;
  __syncthreads();
  if (tid == 0) {
    float v = 0.f;
#pragma unroll
    for (int wp = 0; wp < 8; wp++) v += red_s[wp][0];
    g_ts[b * T + t] = v;
  }
}

// ---------------------------------------------------------------------------
// Kernel 3: turn softmax + weighted combine. grid = B, 256 threads.
// ---------------------------------------------------------------------------
__global__ __launch_bounds__(256) void combine_kernel(
    const int* __restrict__ turns, float* __restrict__ out) {
  int b = blockIdx.x;
  int nt = turns[b];
  int tid = threadIdx.x;
  __shared__ float attn[T];
  if (tid < 32) {  // T == 32, one warp does the softmax
    float s = (tid < nt) ? g_ts[b * T + tid] : -CUDART_INF_F;
    float mx = s;
#pragma unroll
    for (int off = 16; off; off >>= 1)
      mx = fmaxf(mx, __shfl_xor_sync(0xffffffffu, mx, off));
    float e = (tid < nt) ? __expf(s - mx) : 0.f;
    float sm = e;
#pragma unroll
    for (int off = 16; off; off >>= 1)
      sm += __shfl_xor_sync(0xffffffffu, sm, off);
    attn[tid] = e / sm;
  }
  __syncthreads();
  int c4 = tid * 4;
  float4 acc = make_float4(0.f, 0.f, 0.f, 0.f);
  for (int t = 0; t < nt; t++) {
    float a = attn[t];
    float4 cw = *reinterpret_cast<const float4*>(g_cw + (b * T + t) * D + c4);
    acc.x = fmaf(a, cw.x, acc.x);
    acc.y = fmaf(a, cw.y, acc.y);
    acc.z = fmaf(a, cw.z, acc.z);
    acc.w = fmaf(a, cw.w, acc.w);
  }
  *reinterpret_cast<float4*>(out + b * D + c4) = acc;
}

// ---------------------------------------------------------------------------
extern "C" void kernel_launch(void* const* d_in, const int* in_sizes, int n_in,
                              void* d_out, int out_size) {
  // Resolve inputs by element count (defensive; W_word precedes W_turn).
  const float *src = nullptr, *bank = nullptr, *Wword = nullptr, *Wturn = nullptr;
  const int *lens = nullptr, *turns = nullptr;
  for (int i = 0; i < n_in; i++) {
    switch (in_sizes[i]) {
      case B * D:            src  = (const float*)d_in[i]; break;
      case B * T * WW * D:   bank = (const float*)d_in[i]; break;
      case B * T:            lens = (const int*)d_in[i];   break;
      case B:                turns = (const int*)d_in[i];  break;
      case D * D:
        if (!Wword) Wword = (const float*)d_in[i];
        else        Wturn = (const float*)d_in[i];
        break;
      default: break;
    }
  }
  proj_part_kernel<<<2 * 4 * NDBLK, 256>>>(src, Wword, Wturn);
  attn_kernel<<<dim3(T, B), 256>>>(bank, lens, turns);
  combine_kernel<<<B, 256>>>(turns, (float*)d_out);
}

// round 2
// speedup vs baseline: 1.4082x; 1.4082x over previous
#include <cuda_runtime.h>
#include <math_constants.h>

#define B 16
#define T 32
#define WW 128
#define D 1024
#define NDBLK 64       // d-chunks for projection partials
#define DCHUNK (D / NDBLK)  // 16

// Scratch (no device allocation allowed)
__device__ float g_part[2 * NDBLK * B * D];  // [mat][dblk][b][c]  (32 MB)
__device__ float g_q[2 * B * D];             // reduced projections [mat][b][c]
__device__ float g_cw[B * T * D];            // word-attended context per turn
__device__ float g_ts[B * T];                // turn scores

// ---------------------------------------------------------------------------
// Kernel 1: partial projections  q = source @ W  (W stored [indim, outdim]).
// grid = (NDBLK, 2 b-halves, 2 mats) = 256 blocks, 256 threads.
// Each thread: 4 consecutive output cols (float4 W loads), 16-deep d slice,
// 8 batch rows. Fully unrolled -> ~16 float4 loads in flight per thread.
// ---------------------------------------------------------------------------
__global__ __launch_bounds__(256) void proj_part_kernel(
    const float* __restrict__ src, const float* __restrict__ Wword,
    const float* __restrict__ Wturn) {
  int dblk = blockIdx.x;
  int b0 = blockIdx.y * 8;
  int mat = blockIdx.z;
  const float* __restrict__ Wm = mat ? Wturn : Wword;
  int c4 = threadIdx.x * 4;
  int d0 = dblk * DCHUNK;

  __shared__ float s_src[DCHUNK][8];
  if (threadIdx.x < DCHUNK * 8) {
    int dl = threadIdx.x >> 3, bb = threadIdx.x & 7;
    s_src[dl][bb] = src[(b0 + bb) * D + d0 + dl];
  }
  __syncthreads();

  float4 acc[8];
#pragma unroll
  for (int bb = 0; bb < 8; bb++) acc[bb] = make_float4(0.f, 0.f, 0.f, 0.f);

#pragma unroll
  for (int dl = 0; dl < DCHUNK; dl++) {
    float4 wv = *reinterpret_cast<const float4*>(&Wm[(d0 + dl) * D + c4]);
#pragma unroll
    for (int bb = 0; bb < 8; bb++) {
      float s = s_src[dl][bb];
      acc[bb].x = fmaf(s, wv.x, acc[bb].x);
      acc[bb].y = fmaf(s, wv.y, acc[bb].y);
      acc[bb].z = fmaf(s, wv.z, acc[bb].z);
      acc[bb].w = fmaf(s, wv.w, acc[bb].w);
    }
  }

#pragma unroll
  for (int bb = 0; bb < 8; bb++) {
    float* outp = g_part + ((long)(mat * NDBLK + dblk) * B + (b0 + bb)) * D + c4;
    *reinterpret_cast<float4*>(outp) = acc[bb];
  }
}

// ---------------------------------------------------------------------------
// Kernel 2: reduce NDBLK partials -> g_q[2][B][D]. L2-resident (8 MB).
// grid = 32, 256 threads; one float4 output per thread.
// ---------------------------------------------------------------------------
__global__ __launch_bounds__(256) void reduce_q_kernel() {
  int idx = blockIdx.x * 256 + threadIdx.x;  // 0..8191 over [2][16][256]
  int mat = idx >> 12;
  int b = (idx >> 8) & 15;
  int c4 = (idx & 255) * 4;
  float4 sum = make_float4(0.f, 0.f, 0.f, 0.f);
#pragma unroll
  for (int j = 0; j < NDBLK; j++) {
    float4 p = *reinterpret_cast<const float4*>(
        g_part + ((long)(mat * NDBLK + j) * B + b) * D + c4);
    sum.x += p.x; sum.y += p.y; sum.z += p.z; sum.w += p.w;
  }
  *reinterpret_cast<float4*>(g_q + (mat * B + b) * D + c4) = sum;
}

// ---------------------------------------------------------------------------
// Kernel 3: per-(b,t) word attention, online softmax, 8 rows/chunk,
// software-prefetched next chunk (loads issued before the barrier).
// ---------------------------------------------------------------------------
__global__ __launch_bounds__(256) void attn_kernel(
    const float* __restrict__ bank, const int* __restrict__ lens,
    const int* __restrict__ turns) {
  int t = blockIdx.x, b = blockIdx.y;
  if (t >= turns[b]) return;  // masked turn: contributes exactly 0 downstream
  int len = lens[b * T + t];
  int tid = threadIdx.x;
  int c4 = tid * 4;

  float4 qw = *reinterpret_cast<const float4*>(g_q + b * D + c4);
  float4 qt = *reinterpret_cast<const float4*>(g_q + (B + b) * D + c4);

  const float* __restrict__ base = bank + (long)(b * T + t) * WW * D;

  __shared__ float red_s[8][8];   // [warp][row]
  __shared__ float bcast[12];

  float4 cur[8], nxt[8];
#pragma unroll
  for (int i = 0; i < 8; i++) {
    cur[i] = (i < len) ? *reinterpret_cast<const float4*>(base + i * D + c4)
                       : make_float4(0.f, 0.f, 0.f, 0.f);
  }

  float4 acc = make_float4(0.f, 0.f, 0.f, 0.f);
  float m_run = -CUDART_INF_F, sum_run = 0.f;  // live in warp 0

  for (int w0 = 0; w0 < len; w0 += 8) {
    float p[8];
#pragma unroll
    for (int i = 0; i < 8; i++)
      p[i] = fmaf(qw.x, cur[i].x,
             fmaf(qw.y, cur[i].y, fmaf(qw.z, cur[i].z, qw.w * cur[i].w)));
#pragma unroll
    for (int off = 16; off; off >>= 1) {
#pragma unroll
      for (int i = 0; i < 8; i++) p[i] += __shfl_down_sync(0xffffffffu, p[i], off);
    }
    if ((tid & 31) == 0) {
      int wp = tid >> 5;
#pragma unroll
      for (int i = 0; i < 8; i++) red_s[wp][i] = p[i];
    }
    // Prefetch next chunk BEFORE the barrier so DRAM latency overlaps the
    // reduce/softmax/accumulate of this chunk.
#pragma unroll
    for (int i = 0; i < 8; i++) {
      int w = w0 + 8 + i;
      nxt[i] = (w < len) ? *reinterpret_cast<const float4*>(base + w * D + c4)
                         : make_float4(0.f, 0.f, 0.f, 0.f);
    }
    __syncthreads();
    if (tid < 32) {
      int row = tid & 7, wp = tid >> 3;  // wp 0..3
      float v = red_s[wp][row] + red_s[wp + 4][row];
      v += __shfl_xor_sync(0xffffffffu, v, 8);
      v += __shfl_xor_sync(0xffffffffu, v, 16);
      float s[8];
#pragma unroll
      for (int i = 0; i < 8; i++) s[i] = __shfl_sync(0xffffffffu, v, i);
      float m_new = m_run;
#pragma unroll
      for (int i = 0; i < 8; i++)
        if (w0 + i < len) m_new = fmaxf(m_new, s[i]);
      float sc = __expf(m_run - m_new);  // 0 when m_run == -inf
      float e[8], esum = 0.f;
#pragma unroll
      for (int i = 0; i < 8; i++) {
        e[i] = (w0 + i < len) ? __expf(s[i] - m_new) : 0.f;
        esum += e[i];
      }
      sum_run = fmaf(sum_run, sc, esum);
      m_run = m_new;
      if (tid == 0) {
#pragma unroll
        for (int i = 0; i < 8; i++) bcast[i] = e[i];
        bcast[8] = sc;
      }
    }
    __syncthreads();
    float sc = bcast[8];
    float w0v = bcast[0], w1v = bcast[1], w2v = bcast[2], w3v = bcast[3];
    float w4v = bcast[4], w5v = bcast[5], w6v = bcast[6], w7v = bcast[7];
    acc.x = acc.x * sc;
    acc.y = acc.y * sc;
    acc.z = acc.z * sc;
    acc.w = acc.w * sc;
    acc.x = fmaf(w0v, cur[0].x, fmaf(w1v, cur[1].x, fmaf(w2v, cur[2].x, fmaf(w3v, cur[3].x, acc.x))));
    acc.x = fmaf(w4v, cur[4].x, fmaf(w5v, cur[5].x, fmaf(w6v, cur[6].x, fmaf(w7v, cur[7].x, acc.x))));
    acc.y = fmaf(w0v, cur[0].y, fmaf(w1v, cur[1].y, fmaf(w2v, cur[2].y, fmaf(w3v, cur[3].y, acc.y))));
    acc.y = fmaf(w4v, cur[4].y, fmaf(w5v, cur[5].y, fmaf(w6v, cur[6].y, fmaf(w7v, cur[7].y, acc.y))));
    acc.z = fmaf(w0v, cur[0].z, fmaf(w1v, cur[1].z, fmaf(w2v, cur[2].z, fmaf(w3v, cur[3].z, acc.z))));
    acc.z = fmaf(w4v, cur[4].z, fmaf(w5v, cur[5].z, fmaf(w6v, cur[6].z, fmaf(w7v, cur[7].z, acc.z))));
    acc.w = fmaf(w0v, cur[0].w, fmaf(w1v, cur[1].w, fmaf(w2v, cur[2].w, fmaf(w3v, cur[3].w, acc.w))));
    acc.w = fmaf(w4v, cur[4].w, fmaf(w5v, cur[5].w, fmaf(w6v, cur[6].w, fmaf(w7v, cur[7].w, acc.w))));
#pragma unroll
    for (int i = 0; i < 8; i++) cur[i] = nxt[i];
  }

  if (tid == 0) bcast[9] = sum_run;
  __syncthreads();
  float inv = 1.f / bcast[9];
  float4 cw = make_float4(acc.x * inv, acc.y * inv, acc.z * inv, acc.w * inv);
  *reinterpret_cast<float4*>(g_cw + (b * T + t) * D + c4) = cw;

  // turn score: q_t . cw (block reduce)
  float tp = fmaf(qt.x, cw.x, fmaf(qt.y, cw.y, fmaf(qt.z, cw.z, qt.w * cw.w)));
#pragma unroll
  for (int off = 16; off; off >>= 1) tp += __shfl_down_sync(0xffffffffu, tp, off);
  if ((tid & 31) == 0) red_s[tid >> 5][0] = tp;
  __syncthreads();
  if (tid == 0) {
    float v = 0.f;
#pragma unroll
    for (int wp = 0; wp < 8; wp++) v += red_s[wp][0];
    g_ts[b * T + t] = v;
  }
}

// ---------------------------------------------------------------------------
// Kernel 4: turn softmax + weighted combine. grid = B, 256 threads.
// ---------------------------------------------------------------------------
__global__ __launch_bounds__(256) void combine_kernel(
    const int* __restrict__ turns, float* __restrict__ out) {
  int b = blockIdx.x;
  int nt = turns[b];
  int tid = threadIdx.x;
  __shared__ float attn[T];
  if (tid < 32) {  // T == 32
    float s = (tid < nt) ? g_ts[b * T + tid] : -CUDART_INF_F;
    float mx = s;
#pragma unroll
    for (int off = 16; off; off >>= 1)
      mx = fmaxf(mx, __shfl_xor_sync(0xffffffffu, mx, off));
    float e = (tid < nt) ? __expf(s - mx) : 0.f;
    float sm = e;
#pragma unroll
    for (int off = 16; off; off >>= 1)
      sm += __shfl_xor_sync(0xffffffffu, sm, off);
    attn[tid] = e / sm;
  }
  __syncthreads();
  int c4 = tid * 4;
  float4 acc = make_float4(0.f, 0.f, 0.f, 0.f);
  for (int t = 0; t < nt; t++) {
    float a = attn[t];
    float4 cw = *reinterpret_cast<const float4*>(g_cw + (b * T + t) * D + c4);
    acc.x = fmaf(a, cw.x, acc.x);
    acc.y = fmaf(a, cw.y, acc.y);
    acc.z = fmaf(a, cw.z, acc.z);
    acc.w = fmaf(a, cw.w, acc.w);
  }
  *reinterpret_cast<float4*>(out + b * D + c4) = acc;
}

// ---------------------------------------------------------------------------
extern "C" void kernel_launch(void* const* d_in, const int* in_sizes, int n_in,
                              void* d_out, int out_size) {
  const float *src = nullptr, *bank = nullptr, *Wword = nullptr, *Wturn = nullptr;
  const int *lens = nullptr, *turns = nullptr;
  for (int i = 0; i < n_in; i++) {
    switch (in_sizes[i]) {
      case B * D:            src  = (const float*)d_in[i]; break;
      case B * T * WW * D:   bank = (const float*)d_in[i]; break;
      case B * T:            lens = (const int*)d_in[i];   break;
      case B:                turns = (const int*)d_in[i];  break;
      case D * D:
        if (!Wword) Wword = (const float*)d_in[i];
        else        Wturn = (const float*)d_in[i];
        break;
      default: break;
    }
  }
  proj_part_kernel<<<dim3(NDBLK, 2, 2), 256>>>(src, Wword, Wturn);
  reduce_q_kernel<<<32, 256>>>();
  attn_kernel<<<dim3(T, B), 256>>>(bank, lens, turns);
  combine_kernel<<<B, 256>>>(turns, (float*)d_out);
}

// round 3
// speedup vs baseline: 1.6546x; 1.1750x over previous
#include <cuda_runtime.h>
#include <math_constants.h>

#define B 16
#define T 32
#define WW 128
#define D 1024
#define NDBLK 32            // d-chunks for projection partials
#define DCHUNK (D / NDBLK)  // 32

// Scratch (no device allocation allowed). Zero-initialized .bss: masked-turn
// rows of g_cw are never written and stay exactly 0.
__device__ float g_part[2 * NDBLK * B * D];
__device__ float g_q[2 * B * D];
__device__ float g_cw[B * T * D];
__device__ float g_ts[B * T];

// ---------------------------------------------------------------------------
// Kernel 1: partial projections q = source @ W (W stored [indim, outdim]).
// grid = (NDBLK, 2 b-halves, 2 mats) = 128 blocks, 256 threads.
// Thread: 4 output cols (float4 W loads), 32-deep d slice, 8 batch rows.
// ---------------------------------------------------------------------------
__global__ __launch_bounds__(256) void proj_part_kernel(
    const float* __restrict__ src, const float* __restrict__ Wword,
    const float* __restrict__ Wturn) {
  int dblk = blockIdx.x;
  int b0 = blockIdx.y * 8;
  int mat = blockIdx.z;
  const float* __restrict__ Wm = mat ? Wturn : Wword;
  int c4 = threadIdx.x * 4;
  int d0 = dblk * DCHUNK;

  __shared__ float s_src[DCHUNK][8];
  {
    int dl = threadIdx.x >> 3, bb = threadIdx.x & 7;  // 32*8 == 256
    s_src[dl][bb] = src[(b0 + bb) * D + d0 + dl];
  }
  __syncthreads();

  float4 acc[8];
#pragma unroll
  for (int bb = 0; bb < 8; bb++) acc[bb] = make_float4(0.f, 0.f, 0.f, 0.f);

#pragma unroll
  for (int dl = 0; dl < DCHUNK; dl++) {
    float4 wv = *reinterpret_cast<const float4*>(&Wm[(d0 + dl) * D + c4]);
#pragma unroll
    for (int bb = 0; bb < 8; bb++) {
      float s = s_src[dl][bb];
      acc[bb].x = fmaf(s, wv.x, acc[bb].x);
      acc[bb].y = fmaf(s, wv.y, acc[bb].y);
      acc[bb].z = fmaf(s, wv.z, acc[bb].z);
      acc[bb].w = fmaf(s, wv.w, acc[bb].w);
    }
  }

#pragma unroll
  for (int bb = 0; bb < 8; bb++) {
    float* outp = g_part + ((long)(mat * NDBLK + dblk) * B + (b0 + bb)) * D + c4;
    *reinterpret_cast<float4*>(outp) = acc[bb];
  }
}

// ---------------------------------------------------------------------------
// Kernel 2: reduce NDBLK partials -> g_q[2][B][D]. grid = 32 x 256.
// ---------------------------------------------------------------------------
__global__ __launch_bounds__(256) void reduce_q_kernel() {
  int idx = blockIdx.x * 256 + threadIdx.x;  // [2][16][256 float4]
  int mat = idx >> 12;
  int b = (idx >> 8) & 15;
  int c4 = (idx & 255) * 4;
  float4 sum = make_float4(0.f, 0.f, 0.f, 0.f);
#pragma unroll
  for (int j = 0; j < NDBLK; j++) {
    float4 p = *reinterpret_cast<const float4*>(
        g_part + ((long)(mat * NDBLK + j) * B + b) * D + c4);
    sum.x += p.x; sum.y += p.y; sum.z += p.z; sum.w += p.w;
  }
  *reinterpret_cast<float4*>(g_q + (mat * B + b) * D + c4) = sum;
}

// ---------------------------------------------------------------------------
// Kernel 3: per-(b,t) word attention. Warp-private online softmax, no
// barriers in the main loop. Warp wp handles rows wp, wp+8, ... (2 per iter);
// each lane owns 8 strided float4 column segments (full D per warp).
// Single end-of-kernel merge across 8 warps through smem.
// ---------------------------------------------------------------------------
__global__ __launch_bounds__(256) void attn_kernel(
    const float* __restrict__ bank, const int* __restrict__ lens,
    const int* __restrict__ turns) {
  int t = blockIdx.x, b = blockIdx.y;
  if (t >= turns[b]) return;  // masked turn: contributes exactly 0 downstream
  int len = lens[b * T + t];
  int tid = threadIdx.x, wp = tid >> 5, lane = tid & 31;

  // lane owns cols j*128 + lane*4, j = 0..7
  float4 qw[8];
#pragma unroll
  for (int j = 0; j < 8; j++)
    qw[j] = *reinterpret_cast<const float4*>(g_q + b * D + j * 128 + lane * 4);

  const float* __restrict__ base = bank + (long)(b * T + t) * WW * D;

  float m = -CUDART_INF_F, ssum = 0.f;
  float4 acc[8];
#pragma unroll
  for (int j = 0; j < 8; j++) acc[j] = make_float4(0.f, 0.f, 0.f, 0.f);

  int w = wp;
#pragma unroll 1
  for (; w + 8 < len; w += 16) {  // two rows per iteration: w, w+8
    float4 r0[8], r1[8];
#pragma unroll
    for (int j = 0; j < 8; j++)
      r0[j] = *reinterpret_cast<const float4*>(base + w * D + j * 128 + lane * 4);
#pragma unroll
    for (int j = 0; j < 8; j++)
      r1[j] = *reinterpret_cast<const float4*>(base + (w + 8) * D + j * 128 + lane * 4);

    float p0 = 0.f, p1 = 0.f;
#pragma unroll
    for (int j = 0; j < 8; j++) {
      p0 = fmaf(qw[j].x, r0[j].x, fmaf(qw[j].y, r0[j].y,
           fmaf(qw[j].z, r0[j].z, fmaf(qw[j].w, r0[j].w, p0))));
      p1 = fmaf(qw[j].x, r1[j].x, fmaf(qw[j].y, r1[j].y,
           fmaf(qw[j].z, r1[j].z, fmaf(qw[j].w, r1[j].w, p1))));
    }
#pragma unroll
    for (int off = 16; off; off >>= 1) {
      p0 += __shfl_xor_sync(0xffffffffu, p0, off);
      p1 += __shfl_xor_sync(0xffffffffu, p1, off);
    }
    float mnew = fmaxf(m, fmaxf(p0, p1));
    float sc = __expf(m - mnew);        // 0 on first iteration (m = -inf)
    float e0 = __expf(p0 - mnew);
    float e1 = __expf(p1 - mnew);
    ssum = fmaf(ssum, sc, e0 + e1);
    m = mnew;
#pragma unroll
    for (int j = 0; j < 8; j++) {
      acc[j].x = fmaf(e1, r1[j].x, fmaf(e0, r0[j].x, acc[j].x * sc));
      acc[j].y = fmaf(e1, r1[j].y, fmaf(e0, r0[j].y, acc[j].y * sc));
      acc[j].z = fmaf(e1, r1[j].z, fmaf(e0, r0[j].z, acc[j].z * sc));
      acc[j].w = fmaf(e1, r1[j].w, fmaf(e0, r0[j].w, acc[j].w * sc));
    }
  }
  if (w < len) {  // tail row
    float4 r0[8];
#pragma unroll
    for (int j = 0; j < 8; j++)
      r0[j] = *reinterpret_cast<const float4*>(base + w * D + j * 128 + lane * 4);
    float p0 = 0.f;
#pragma unroll
    for (int j = 0; j < 8; j++)
      p0 = fmaf(qw[j].x, r0[j].x, fmaf(qw[j].y, r0[j].y,
           fmaf(qw[j].z, r0[j].z, fmaf(qw[j].w, r0[j].w, p0))));
#pragma unroll
    for (int off = 16; off; off >>= 1) p0 += __shfl_xor_sync(0xffffffffu, p0, off);
    float mnew = fmaxf(m, p0);
    float sc = __expf(m - mnew);
    float e0 = __expf(p0 - mnew);
    ssum = fmaf(ssum, sc, e0);
    m = mnew;
#pragma unroll
    for (int j = 0; j < 8; j++) {
      acc[j].x = fmaf(e0, r0[j].x, acc[j].x * sc);
      acc[j].y = fmaf(e0, r0[j].y, acc[j].y * sc);
      acc[j].z = fmaf(e0, r0[j].z, acc[j].z * sc);
      acc[j].w = fmaf(e0, r0[j].w, acc[j].w * sc);
    }
  }

  // ---- merge 8 warp-private (m, ssum, acc) states ----
  __shared__ float s_ms[8][2];
  __shared__ __align__(16) float s_acc[8][D];  // 32 KB
  if (lane == 0) { s_ms[wp][0] = m; s_ms[wp][1] = ssum; }
  __syncthreads();
  float M = -CUDART_INF_F;
#pragma unroll
  for (int k = 0; k < 8; k++) M = fmaxf(M, s_ms[k][0]);
  float S = 0.f;
#pragma unroll
  for (int k = 0; k < 8; k++) S += s_ms[k][1] * __expf(s_ms[k][0] - M);
  float wt = __expf(m - M);  // 0 for warps that saw no rows (m = -inf)
#pragma unroll
  for (int j = 0; j < 8; j++) {
    float4 v = make_float4(acc[j].x * wt, acc[j].y * wt, acc[j].z * wt, acc[j].w * wt);
    *reinterpret_cast<float4*>(&s_acc[wp][j * 128 + lane * 4]) = v;
  }
  __syncthreads();

  int c4 = tid * 4;
  float4 sum = make_float4(0.f, 0.f, 0.f, 0.f);
#pragma unroll
  for (int k = 0; k < 8; k++) {
    float4 v = *reinterpret_cast<const float4*>(&s_acc[k][c4]);
    sum.x += v.x; sum.y += v.y; sum.z += v.z; sum.w += v.w;
  }
  float inv = 1.f / S;
  float4 cw = make_float4(sum.x * inv, sum.y * inv, sum.z * inv, sum.w * inv);
  *reinterpret_cast<float4*>(g_cw + (b * T + t) * D + c4) = cw;

  // turn score: q_t . cw (block reduce)
  float4 qt = *reinterpret_cast<const float4*>(g_q + (B + b) * D + c4);
  float tp = fmaf(qt.x, cw.x, fmaf(qt.y, cw.y, fmaf(qt.z, cw.z, qt.w * cw.w)));
#pragma unroll
  for (int off = 16; off; off >>= 1) tp += __shfl_down_sync(0xffffffffu, tp, off);
  if (lane == 0) s_ms[wp][0] = tp;  // s_ms reads all happened before prior barrier path
  __syncthreads();
  if (tid == 0) {
    float v = 0.f;
#pragma unroll
    for (int k = 0; k < 8; k++) v += s_ms[k][0];
    g_ts[b * T + t] = v;
  }
}

// ---------------------------------------------------------------------------
// Kernel 4: turn softmax + combine, FULLY UNROLLED over T (32 independent
// loads in flight; masked turns have exact-zero weight and zero g_cw rows).
// ---------------------------------------------------------------------------
__global__ __launch_bounds__(256) void combine_kernel(
    const int* __restrict__ turns, float* __restrict__ out) {
  int b = blockIdx.x;
  int nt = turns[b];
  int tid = threadIdx.x;
  __shared__ float attn[T];
  if (tid < 32) {  // T == 32
    float s = (tid < nt) ? g_ts[b * T + tid] : -CUDART_INF_F;
    float mx = s;
#pragma unroll
    for (int off = 16; off; off >>= 1)
      mx = fmaxf(mx, __shfl_xor_sync(0xffffffffu, mx, off));
    float e = (tid < nt) ? __expf(s - mx) : 0.f;
    float sm = e;
#pragma unroll
    for (int off = 16; off; off >>= 1)
      sm += __shfl_xor_sync(0xffffffffu, sm, off);
    attn[tid] = e / sm;
  }
  __syncthreads();
  int c4 = tid * 4;
  float4 acc = make_float4(0.f, 0.f, 0.f, 0.f);
#pragma unroll
  for (int t = 0; t < T; t++) {
    float a = attn[t];
    float4 cw = *reinterpret_cast<const float4*>(g_cw + (b * T + t) * D + c4);
    acc.x = fmaf(a, cw.x, acc.x);
    acc.y = fmaf(a, cw.y, acc.y);
    acc.z = fmaf(a, cw.z, acc.z);
    acc.w = fmaf(a, cw.w, acc.w);
  }
  *reinterpret_cast<float4*>(out + b * D + c4) = acc;
}

// ---------------------------------------------------------------------------
extern "C" void kernel_launch(void* const* d_in, const int* in_sizes, int n_in,
                              void* d_out, int out_size) {
  const float *src = nullptr, *bank = nullptr, *Wword = nullptr, *Wturn = nullptr;
  const int *lens = nullptr, *turns = nullptr;
  for (int i = 0; i < n_in; i++) {
    switch (in_sizes[i]) {
      case B * D:            src  = (const float*)d_in[i]; break;
      case B * T * WW * D:   bank = (const float*)d_in[i]; break;
      case B * T:            lens = (const int*)d_in[i];   break;
      case B:                turns = (const int*)d_in[i];  break;
      case D * D:
        if (!Wword) Wword = (const float*)d_in[i];
        else        Wturn = (const float*)d_in[i];
        break;
      default: break;
    }
  }
  proj_part_kernel<<<dim3(NDBLK, 2, 2), 256>>>(src, Wword, Wturn);
  reduce_q_kernel<<<32, 256>>>();
  attn_kernel<<<dim3(T, B), 256>>>(bank, lens, turns);
  combine_kernel<<<B, 256>>>(turns, (float*)d_out);
}